// round 8
// baseline (speedup 1.0000x reference)
#include <cuda_runtime.h>
#include <math.h>

#define N 1024
#define NN (N*N)
#define NB 32

// ---------------- scratch (device globals; no allocations allowed) -------------
__device__ float g_lu[16 * NN];        // LU workspace
__device__ float g_u12[16 * 32 * N];   // staged U12 per step
__device__ int   g_rowmap[2][16][N];   // ping-pong logical->physical row map
__device__ float g_y[3 * NN];
__device__ float g_part[4 * NN];
__device__ float g_scores[16];
__device__ int   g_top[8];
__device__ int   g_gate;
__device__ float g_weff[11];

// ---------------- init ---------------------------------------------------------
__global__ void init_kernel(const float4* __restrict__ x4) {
    size_t n4 = (size_t)16 * NN / 4;
    for (size_t i = (size_t)blockIdx.x * blockDim.x + threadIdx.x; i < n4;
         i += (size_t)gridDim.x * blockDim.x)
        ((float4*)g_lu)[i] = x4[i];
}

// ---------------- panel: register-resident factor + full-width U12 staging -----
// 16 CTAs, 512 threads. Each thread owns 2 rows (32 cols) in registers.
__global__ __launch_bounds__(512) void panel_kernel(int kb) {
    __shared__ float xj[32], xb[32];      // exchange rows
    __shared__ float swv[16];
    __shared__ int   swp[16];
    __shared__ int   s_bp, s_xpj, s_xpb;
    __shared__ float l11[32 * 33];
    __shared__ int   phys32[32];

    int m = blockIdx.x, tid = threadIdx.x;
    int lane = tid & 31, wid = tid >> 5;
    float* A = g_lu + (size_t)m * NN;
    int col0 = kb * NB;
    int Ru = N - col0;
    const int* map_in = g_rowmap[kb & 1][m];
    int* map_out = g_rowmap[(kb + 1) & 1][m];

    int pos0 = 2 * tid, pos1 = 2 * tid + 1;
    bool act0 = pos0 < Ru, act1 = pos1 < Ru;
    float a0[32], a1[32];
    int ph0 = 0, ph1 = 0;

    if (act0) {
        ph0 = (kb == 0) ? (col0 + pos0) : map_in[col0 + pos0];
        const float4* p = (const float4*)&A[(size_t)ph0 * N + col0];
        #pragma unroll
        for (int q = 0; q < 8; q++) {
            float4 v = p[q];
            a0[q*4] = v.x; a0[q*4+1] = v.y; a0[q*4+2] = v.z; a0[q*4+3] = v.w;
        }
    }
    if (act1) {
        ph1 = (kb == 0) ? (col0 + pos1) : map_in[col0 + pos1];
        const float4* p = (const float4*)&A[(size_t)ph1 * N + col0];
        #pragma unroll
        for (int q = 0; q < 8; q++) {
            float4 v = p[q];
            a1[q*4] = v.x; a1[q*4+1] = v.y; a1[q*4+2] = v.z; a1[q*4+3] = v.w;
        }
    }
    __syncthreads();

    float logsum = 0.0f;
    #pragma unroll
    for (int j = 0; j < 32; j++) {
        // ---- pivot search over positions >= j ----
        float bv = -1.0f; int bp = 1 << 30;
        if (act0 && pos0 >= j) { bv = fabsf(a0[j]); bp = pos0; }
        if (act1 && pos1 >= j) {
            float v = fabsf(a1[j]);
            if (v > bv || (v == bv && pos1 < bp)) { bv = v; bp = pos1; }
        }
        #pragma unroll
        for (int off = 16; off; off >>= 1) {
            float ov = __shfl_down_sync(0xffffffffu, bv, off);
            int   op = __shfl_down_sync(0xffffffffu, bp, off);
            if (ov > bv || (ov == bv && op < bp)) { bv = ov; bp = op; }
        }
        if (lane == 0) { swv[wid] = bv; swp[wid] = bp; }
        __syncthreads();
        if (tid == 0) {
            float b0 = swv[0]; int p0 = swp[0];
            #pragma unroll
            for (int w = 1; w < 16; w++)
                if (swv[w] > b0 || (swv[w] == b0 && swp[w] < p0)) { b0 = swv[w]; p0 = swp[w]; }
            s_bp = p0;
        }
        __syncthreads();
        int piv = s_bp;
        // ---- exchange row j <-> row piv via smem ----
        if (act0 && pos0 == j) {
            #pragma unroll
            for (int c = 0; c < 32; c++) xj[c] = a0[c];
            s_xpj = ph0;
        }
        if (act1 && pos1 == j) {
            #pragma unroll
            for (int c = 0; c < 32; c++) xj[c] = a1[c];
            s_xpj = ph1;
        }
        if (act0 && pos0 == piv) {
            #pragma unroll
            for (int c = 0; c < 32; c++) xb[c] = a0[c];
            s_xpb = ph0;
        }
        if (act1 && pos1 == piv) {
            #pragma unroll
            for (int c = 0; c < 32; c++) xb[c] = a1[c];
            s_xpb = ph1;
        }
        __syncthreads();
        if (act0 && pos0 == j) {
            #pragma unroll
            for (int c = 0; c < 32; c++) a0[c] = xb[c];
            ph0 = s_xpb;
        }
        if (act1 && pos1 == j) {
            #pragma unroll
            for (int c = 0; c < 32; c++) a1[c] = xb[c];
            ph1 = s_xpb;
        }
        if (piv != j) {
            if (act0 && pos0 == piv) {
                #pragma unroll
                for (int c = 0; c < 32; c++) a0[c] = xj[c];
                ph0 = s_xpj;
            }
            if (act1 && pos1 == piv) {
                #pragma unroll
                for (int c = 0; c < 32; c++) a1[c] = xj[c];
                ph1 = s_xpj;
            }
        }
        if (tid == 0) logsum += logf(fabsf(xb[j]));
        // ---- rank-1 update: urow = xb (new row j), all register FMA ----
        float u = xb[j];
        float inv = 1.0f / u;
        bool u0 = act0 && pos0 > j, u1 = act1 && pos1 > j;
        float l0 = u0 ? a0[j] * inv : 0.0f;
        float l1 = u1 ? a1[j] * inv : 0.0f;
        if (u0) a0[j] = l0;
        if (u1) a1[j] = l1;
        #pragma unroll
        for (int c = 0; c < 32; c++) {
            if (c > j) {
                float uc = xb[c];
                a0[c] -= l0 * uc;
                a1[c] -= l1 * uc;
            }
        }
        __syncthreads();
    }
    if (tid == 0) {
        if (kb == 0) g_scores[m] = logsum;
        else         g_scores[m] += logsum;
    }
    // ---- writeback panel, map, and L11/phys32 for trsm ----
    if (act0) {
        float4* p = (float4*)&A[(size_t)ph0 * N + col0];
        #pragma unroll
        for (int q = 0; q < 8; q++) {
            float4 v = {a0[q*4], a0[q*4+1], a0[q*4+2], a0[q*4+3]};
            p[q] = v;
        }
        map_out[col0 + pos0] = ph0;
        if (pos0 < 32) {
            #pragma unroll
            for (int c = 0; c < 32; c++) l11[pos0 * 33 + c] = a0[c];
            phys32[pos0] = ph0;
        }
    }
    if (act1) {
        float4* p = (float4*)&A[(size_t)ph1 * N + col0];
        #pragma unroll
        for (int q = 0; q < 8; q++) {
            float4 v = {a1[q*4], a1[q*4+1], a1[q*4+2], a1[q*4+3]};
            p[q] = v;
        }
        map_out[col0 + pos1] = ph1;
        if (pos1 < 32) {
            #pragma unroll
            for (int c = 0; c < 32; c++) l11[pos1 * 33 + c] = a1[c];
            phys32[pos1] = ph1;
        }
    }
    __syncthreads();
    // ---- trsm: stage U12 = L11^{-1} A[rows j][trailing cols] into g_u12 ----
    int nb0 = col0 + NB;
    float* U = g_u12 + (size_t)m * 32 * N;
    for (int cc = nb0 + tid; cc < N; cc += 512) {
        float u[32];
        #pragma unroll
        for (int j = 0; j < 32; j++) {
            float s = A[(size_t)phys32[j] * N + cc];
            #pragma unroll
            for (int i = 0; i < 31; i++)
                if (i < j) s -= l11[j * 33 + i] * u[i];
            u[j] = s;
            U[j * N + cc] = s;
        }
    }
}

// ---------------- trailing update: A22 -= L21 @ U12 (128x128 tiles) ------------
__global__ __launch_bounds__(256, 2) void update_kernel(int kb) {
    __shared__ float Bs[32][128];
    __shared__ float LsT[32][132];
    int m = blockIdx.z, tid = threadIdx.x;
    int col0 = kb * NB, nb0 = col0 + NB;
    const int* map = g_rowmap[(kb + 1) & 1][m];
    float* A = g_lu + (size_t)m * NN;
    const float* U = g_u12 + (size_t)m * 32 * N;
    int c0 = nb0 + blockIdx.x * 128;
    int r0 = nb0 + blockIdx.y * 128;

    #pragma unroll
    for (int i = 0; i < 16; i++) {
        int l = tid + i * 256;
        int c = l & 127, kk = l >> 7;
        int cc = c0 + c;
        Bs[kk][c] = (cc < N) ? U[kk * N + cc] : 0.0f;
    }
    #pragma unroll
    for (int i = 0; i < 16; i++) {
        int l = tid + i * 256;
        int r = l >> 5, kk = l & 31;
        int gr = r0 + r;
        LsT[kk][r] = (gr < N) ? A[(size_t)map[gr] * N + col0 + kk] : 0.0f;
    }
    __syncthreads();

    int tx = tid & 15, ty = tid >> 4;
    float acc[8][8] = {};
    #pragma unroll
    for (int kk = 0; kk < 32; kk++) {
        float a[8], b[8];
        *(float4*)&a[0] = *(const float4*)&LsT[kk][ty * 8];
        *(float4*)&a[4] = *(const float4*)&LsT[kk][ty * 8 + 4];
        *(float4*)&b[0] = *(const float4*)&Bs[kk][tx * 8];
        *(float4*)&b[4] = *(const float4*)&Bs[kk][tx * 8 + 4];
        #pragma unroll
        for (int i = 0; i < 8; i++)
            #pragma unroll
            for (int j = 0; j < 8; j++)
                acc[i][j] = fmaf(a[i], b[j], acc[i][j]);
    }
    int gr0 = r0 + ty * 8, gc0 = c0 + tx * 8;
    if (gc0 < N) {
        #pragma unroll
        for (int i = 0; i < 8; i++) {
            int gr = gr0 + i;
            if (gr < N) {
                float4* p = (float4*)&A[(size_t)map[gr] * N + gc0];
                float4 v0 = p[0], v1 = p[1];
                v0.x -= acc[i][0]; v0.y -= acc[i][1]; v0.z -= acc[i][2]; v0.w -= acc[i][3];
                v1.x -= acc[i][4]; v1.y -= acc[i][5]; v1.z -= acc[i][6]; v1.w -= acc[i][7];
                p[0] = v0; p[1] = v1;
            }
        }
    }
}

// ---------------- tail: update + factor trailing 128x128 in smem ---------------
__global__ __launch_bounds__(256) void tail_kernel() {
    extern __shared__ float sm[];
    __shared__ float rv[8];
    __shared__ int   rr[8];
    __shared__ float s_u;
    __shared__ int   s_p;
    int m = blockIdx.x, tid = threadIdx.x;
    float* A = g_lu + (size_t)m * NN;
    const int* map = g_rowmap[0][m];     // (27+1)&1 = 0
    const float* U = g_u12 + (size_t)m * 32 * N;
    const int col0 = 864, nb0 = 896;

    float* u12s = sm;                 // 32 x 128
    float* st   = sm + 4096;          // 128 x 132
    float* lst  = sm + 4096 + 16896;  // 32 x 132

    for (int l = tid; l < 32 * 128; l += 256) {
        int kk = l >> 7, c = l & 127;
        u12s[kk * 128 + c] = U[kk * N + nb0 + c];
    }
    for (int l = tid; l < 128 * 128; l += 256) {
        int r = l >> 7, c = l & 127;
        st[r * 132 + c] = A[(size_t)map[nb0 + r] * N + nb0 + c];
    }
    for (int l = tid; l < 128 * 32; l += 256) {
        int r = l >> 5, kk = l & 31;
        lst[kk * 132 + r] = A[(size_t)map[nb0 + r] * N + col0 + kk];
    }
    __syncthreads();
    // st -= L21 @ U12
    {
        int tx = tid & 15, ty = tid >> 4;
        float acc[8][8] = {};
        #pragma unroll
        for (int kk = 0; kk < 32; kk++) {
            float a[8], b[8];
            *(float4*)&a[0] = *(const float4*)&lst[kk * 132 + ty * 8];
            *(float4*)&a[4] = *(const float4*)&lst[kk * 132 + ty * 8 + 4];
            *(float4*)&b[0] = *(const float4*)&u12s[kk * 128 + tx * 8];
            *(float4*)&b[4] = *(const float4*)&u12s[kk * 128 + tx * 8 + 4];
            #pragma unroll
            for (int i = 0; i < 8; i++)
                #pragma unroll
                for (int j = 0; j < 8; j++)
                    acc[i][j] = fmaf(a[i], b[j], acc[i][j]);
        }
        #pragma unroll
        for (int i = 0; i < 8; i++)
            #pragma unroll
            for (int j = 0; j < 8; j++)
                st[(ty * 8 + i) * 132 + tx * 8 + j] -= acc[i][j];
    }
    __syncthreads();
    // factor 128x128 with partial pivoting (logdet only)
    float logsum = 0.0f;
    for (int j = 0; j < 128; j++) {
        float bv = -1.0f; int br = j;
        if (tid < 128 && tid >= j) {
            bv = fabsf(st[tid * 132 + j]);
            br = tid;
        }
        #pragma unroll
        for (int off = 16; off; off >>= 1) {
            float ov = __shfl_down_sync(0xffffffffu, bv, off);
            int   orr = __shfl_down_sync(0xffffffffu, br, off);
            if (ov > bv || (ov == bv && orr < br)) { bv = ov; br = orr; }
        }
        if ((tid & 31) == 0) { rv[tid >> 5] = bv; rr[tid >> 5] = br; }
        __syncthreads();
        if (tid == 0) {
            float b0 = rv[0]; int r0 = rr[0];
            for (int w = 1; w < 8; w++)
                if (rv[w] > b0 || (rv[w] == b0 && rr[w] < r0)) { b0 = rv[w]; r0 = rr[w]; }
            s_p = r0;
            s_u = st[r0 * 132 + j];
            logsum += logf(fabsf(s_u));
        }
        __syncthreads();
        int p = s_p;
        float u = s_u;
        if (tid < 128 && p != j) {
            float t = st[j * 132 + tid];
            st[j * 132 + tid] = st[p * 132 + tid];
            st[p * 132 + tid] = t;
        }
        __syncthreads();
        if (tid < 128 && tid > j) {
            float lij = st[tid * 132 + j] / u;
            for (int c = j + 1; c < 128; c++)
                st[tid * 132 + c] -= lij * st[j * 132 + c];
        }
        __syncthreads();
    }
    if (tid == 0) g_scores[m] += logsum;
}

// ---------------- top-8 selection + effective-weight collapse ------------------
__global__ void topk_kernel(const int* __restrict__ flags_i32,
                            const float* __restrict__ W1, const float* __restrict__ b1,
                            const float* __restrict__ W2, const float* __restrict__ b2) {
    if (threadIdx.x != 0) return;
    const unsigned char* flags_u8 = (const unsigned char*)flags_i32;
    int w0 = flags_i32[0];
    bool as_bytes = (w0 > 1) || (w0 < 0);
    int f[16];
    for (int i = 0; i < 16; i++)
        f[i] = as_bytes ? (flags_u8[i] != 0) : (flags_i32[i] != 0);
    int s = 0;
    for (int i = 0; i < 16; i++) s += f[i];
    g_gate = (s >= 4) ? 1 : 0;
    const float NEG_INF = -__int_as_float(0x7f800000);
    float sc[16];
    for (int i = 0; i < 16; i++) sc[i] = f[i] ? g_scores[i] : NEG_INF;
    bool used[16] = {};
    for (int k = 0; k < 8; k++) {
        float best = NEG_INF;
        int bi = -1;
        for (int i = 0; i < 16; i++)
            if (!used[i] && (bi < 0 || sc[i] > best)) { best = sc[i]; bi = i; }
        used[bi] = true;
        g_top[k] = bi;
    }
    for (int c = 0; c < 10; c++) {
        float a = 0.0f;
        for (int h = 0; h < 16; h++) a += W2[h] * W1[h * 10 + c];
        g_weff[c] = a;
    }
    float be = b2[0];
    for (int h = 0; h < 16; h++) be += W2[h] * b1[h];
    g_weff[10] = be;
}

// ---------------- Y combos -----------------------------------------------------
__global__ void ycombo_kernel(const float* __restrict__ x) {
    const float* X1 = x + (size_t)g_top[1] * NN;
    const float* X2 = x + (size_t)g_top[2] * NN;
    const float* X3 = x + (size_t)g_top[3] * NN;
    float w0 = g_weff[0], w1 = g_weff[1], w2 = g_weff[2];
    float w3 = g_weff[3], w4 = g_weff[4], w5 = g_weff[5];
    for (int e = blockIdx.x * blockDim.x + threadIdx.x; e < NN;
         e += gridDim.x * blockDim.x) {
        float a = X1[e], b = X2[e], c = X3[e];
        g_y[e]          = w0 * a + w1 * b + w2 * c;
        g_y[NN + e]     = w3 * b + w4 * c;
        g_y[2 * NN + e] = w5 * c;
    }
}

// ---------------- pair GEMM: X[0..2] (1024x3072) @ Y (3072x1024), split-K=4 ----
__global__ __launch_bounds__(256) void pair_gemm(const float* __restrict__ x) {
    __shared__ float As[16][132];
    __shared__ float Bs[16][128];
    int z = blockIdx.z;
    int row0 = blockIdx.y * 128, c0 = blockIdx.x * 128;
    const float* A0 = x + (size_t)g_top[0] * NN;
    const float* A1 = x + (size_t)g_top[1] * NN;
    const float* A2 = x + (size_t)g_top[2] * NN;
    int tid = threadIdx.x;
    float acc[8][8] = {};
    int k0 = z * 768;
    for (int kt = 0; kt < 48; kt++) {
        int kg = k0 + kt * 16;
        const float* Ap = (kg < 1024) ? A0 : ((kg < 2048) ? A1 : A2);
        int kl = kg & 1023;
        #pragma unroll
        for (int i = 0; i < 8; i++) {
            int l = tid + i * 256;
            int kk = l & 15, mm = l >> 4;
            As[kk][mm] = Ap[(size_t)(row0 + mm) * N + kl + kk];
        }
        #pragma unroll
        for (int i = 0; i < 8; i++) {
            int l = tid + i * 256;
            int nn = l & 127, kk = l >> 7;
            Bs[kk][nn] = g_y[(size_t)(kg + kk) * N + c0 + nn];
        }
        __syncthreads();
        int mm0 = (tid >> 4) * 8, nn0 = (tid & 15) * 8;
        #pragma unroll
        for (int kk = 0; kk < 16; kk++) {
            float a[8], b[8];
            *(float4*)&a[0] = *(const float4*)&As[kk][mm0];
            *(float4*)&a[4] = *(const float4*)&As[kk][mm0 + 4];
            *(float4*)&b[0] = *(const float4*)&Bs[kk][nn0];
            *(float4*)&b[4] = *(const float4*)&Bs[kk][nn0 + 4];
            #pragma unroll
            for (int i = 0; i < 8; i++)
                #pragma unroll
                for (int j = 0; j < 8; j++)
                    acc[i][j] = fmaf(a[i], b[j], acc[i][j]);
        }
        __syncthreads();
    }
    float* P = g_part + (size_t)z * NN;
    int mm0 = (tid >> 4) * 8, nn0 = (tid & 15) * 8;
    #pragma unroll
    for (int i = 0; i < 8; i++) {
        float4 v0 = {acc[i][0], acc[i][1], acc[i][2], acc[i][3]};
        float4 v1 = {acc[i][4], acc[i][5], acc[i][6], acc[i][7]};
        size_t off = (size_t)(row0 + mm0 + i) * N + c0 + nn0;
        *(float4*)&P[off] = v0;
        *(float4*)&P[off + 4] = v1;
    }
}

// ---------------- epilogue -----------------------------------------------------
__global__ void final_kernel(const float* __restrict__ x, float* __restrict__ out,
                             int out_size) {
    int gate = g_gate;
    const float* P4 = x + (size_t)g_top[4] * NN;
    const float* P5 = x + (size_t)g_top[5] * NN;
    const float* P6 = x + (size_t)g_top[6] * NN;
    const float* P7 = x + (size_t)g_top[7] * NN;
    float w6 = g_weff[6], w7 = g_weff[7], w8 = g_weff[8], w9 = g_weff[9];
    float be = g_weff[10];
    for (int i = blockIdx.x * blockDim.x + threadIdx.x; i < out_size;
         i += gridDim.x * blockDim.x) {
        if (i < NN) {
            float s = g_part[i] + g_part[NN + i] + g_part[2 * NN + i] + g_part[3 * NN + i]
                    + w6 * P4[i] + w7 * P5[i] + w8 * P6[i] + w9 * P7[i] + be;
            out[i] = gate ? (s / (1.0f + expf(-s))) : 0.0f;
        } else {
            out[i] = gate ? 1.0f : 0.0f;
        }
    }
}

// ---------------- host driver --------------------------------------------------
extern "C" void kernel_launch(void* const* d_in, const int* in_sizes, int n_in,
                              void* d_out, int out_size) {
    const float* x = (const float*)d_in[0];
    const int* flags = (const int*)d_in[1];
    const float* W1 = (const float*)d_in[2];
    const float* b1 = (const float*)d_in[3];
    const float* W2 = (const float*)d_in[4];
    const float* b2 = (const float*)d_in[5];
    float* out = (float*)d_out;

    const size_t tail_smem = (4096 + 16896 + 4224) * 4;   // ~100.9 KB
    cudaFuncSetAttribute(tail_kernel, cudaFuncAttributeMaxDynamicSharedMemorySize,
                         tail_smem);

    init_kernel<<<2048, 256>>>((const float4*)x);
    panel_kernel<<<16, 512>>>(0);

    for (int kb = 0; kb < 27; kb++) {
        int Ru = N - (kb + 1) * NB;
        int nt = (Ru + 127) / 128;
        update_kernel<<<dim3(nt, nt, 16), 256>>>(kb);
        panel_kernel<<<16, 512>>>(kb + 1);
    }

    tail_kernel<<<16, 256, tail_smem>>>();
    topk_kernel<<<1, 32>>>(flags, W1, b1, W2, b2);
    ycombo_kernel<<<1024, 256>>>(x);
    pair_gemm<<<dim3(8, 8, 4), 256>>>(x);
    final_kernel<<<1024, 256>>>(x, out, out_size);
}

// round 9
// speedup vs baseline: 1.2288x; 1.2288x over previous
#include <cuda_runtime.h>
#include <math.h>

#define N 1024
#define NN (N*N)
#define NB 32

// ---------------- scratch (device globals) -------------------------------------
__device__ float g_lu[16 * NN];          // LU workspace
__device__ float g_u12[16 * 32 * N];     // staged U12 per step
__device__ float g_l21[16 * N * 32];     // staged L21 (position-major)
__device__ float g_diag[16 * 32 * 33];   // factored 32x32 diag block (L\U)
__device__ float g_invd[16 * 32];        // 1/U11 diag
__device__ int   g_rowmap[16 * N];       // logical->physical row map
__device__ float g_y[3 * NN];
__device__ float g_part[4 * NN];
__device__ float g_scores[16];
__device__ int   g_top[8];
__device__ int   g_gate;
__device__ float g_weff[11];

// ---------------- init: copy x, identity map -----------------------------------
__global__ void init_kernel(const float4* __restrict__ x4) {
    size_t n4 = (size_t)16 * NN / 4;
    for (size_t i = (size_t)blockIdx.x * blockDim.x + threadIdx.x; i < n4;
         i += (size_t)gridDim.x * blockDim.x)
        ((float4*)g_lu)[i] = x4[i];
    for (int i = blockIdx.x * blockDim.x + threadIdx.x; i < 16 * N;
         i += gridDim.x * blockDim.x)
        g_rowmap[i] = i & (N - 1);
}

// ---------------- panel: window-pivoted 128x32 factor in smem ------------------
__global__ __launch_bounds__(256) void panel_kernel(int kb) {
    __shared__ float sp[128][33];
    int m = blockIdx.x, tid = threadIdx.x, lane = tid & 31;
    int col0 = kb * NB;
    int Ru = N - col0;
    int Wn = Ru < 128 ? Ru : 128;
    float* A = g_lu + (size_t)m * NN;
    int* map = g_rowmap + m * N;

    for (int l = tid; l < Wn * 32; l += 256) {
        int w = l >> 5, c = l & 31;
        sp[w][c] = A[(size_t)map[col0 + w] * N + col0 + c];
    }
    __syncthreads();

    float logsum = 0.0f;
    for (int j = 0; j < 32; j++) {
        // redundant per-warp argmax over window rows >= j (4 rows per lane)
        float bv = -1.0f; int bp = 1 << 30;
        #pragma unroll
        for (int q = 0; q < 4; q++) {
            int w = lane + 32 * q;
            if (w >= j && w < Wn) {
                float v = fabsf(sp[w][j]);
                if (v > bv || (v == bv && w < bp)) { bv = v; bp = w; }
            }
        }
        #pragma unroll
        for (int off = 16; off; off >>= 1) {
            float ov = __shfl_xor_sync(0xffffffffu, bv, off);
            int   op = __shfl_xor_sync(0xffffffffu, bp, off);
            if (ov > bv || (ov == bv && op < bp)) { bv = ov; bp = op; }
        }
        int piv = bp;
        float pv = sp[piv][j];            // read BEFORE any swap
        float inv = 1.0f / pv;
        if (tid == 0) logsum += logf(fabsf(pv));
        __syncthreads();                  // BAR1: reads of col j / pivot done
        if (piv != j) {
            if (tid < 32) {
                float t = sp[j][tid];
                sp[j][tid] = sp[piv][tid];
                sp[piv][tid] = t;
            }
            if (tid == 0) {
                int t = map[col0 + j];
                map[col0 + j] = map[col0 + piv];
                map[col0 + piv] = t;
            }
        }
        __syncthreads();                  // BAR2: swap visible
        int r = j + 1 + tid;
        if (r < Wn) {
            float lij = sp[r][j] * inv;
            sp[r][j] = lij;
            for (int c = j + 1; c < 32; c++)
                sp[r][c] -= lij * sp[j][c];
        }
        __syncthreads();                  // BAR3: update visible
    }

    if (tid == 0) {
        if (kb == 0) g_scores[m] = logsum;
        else         g_scores[m] += logsum;
    }
    // diag block + inverse diag
    for (int l = tid; l < 32 * 32; l += 256)
        g_diag[m * 32 * 33 + (l >> 5) * 33 + (l & 31)] = sp[l >> 5][l & 31];
    if (tid < 32) g_invd[m * 32 + tid] = 1.0f / sp[tid][tid];
    // L rows for window positions 0 .. Wn-33
    for (int l = tid; l < (Wn - 32) * 32; l += 256) {
        int p = l >> 5, c = l & 31;
        g_l21[((size_t)m * N + p) * 32 + c] = sp[p + 32][c];
    }
}

// ---------------- lstage: U12 = L11^-1 A12 ; L21 = A21 U11^-1 ------------------
__global__ __launch_bounds__(128) void lstage_kernel(int kb, int ct) {
    __shared__ float d[32][33];
    __shared__ float dinv[32];
    int m = blockIdx.y, tid = threadIdx.x;
    int col0 = kb * NB, nb0 = col0 + NB;
    for (int l = tid; l < 32 * 33; l += 128)
        ((float*)d)[l] = g_diag[m * 32 * 33 + l];
    if (tid < 32) dinv[tid] = g_invd[m * 32 + tid];
    __syncthreads();
    const int* map = g_rowmap + m * N;
    const float* A = g_lu + (size_t)m * NN;

    if (blockIdx.x < ct) {
        int cc = nb0 + blockIdx.x * 128 + tid;
        if (cc < N) {
            float u[32];
            float* U = g_u12 + (size_t)m * 32 * N;
            #pragma unroll
            for (int j = 0; j < 32; j++) {
                float s = A[(size_t)map[col0 + j] * N + cc];
                #pragma unroll
                for (int i = 0; i < 31; i++)
                    if (i < j) s -= d[j][i] * u[i];
                u[j] = s;
                U[j * N + cc] = s;
            }
        }
    } else {
        int lr = col0 + 128 + (blockIdx.x - ct) * 128 + tid;
        if (lr < N) {
            const float* ar = A + (size_t)map[lr] * N + col0;
            float* lrow = g_l21 + ((size_t)m * N + (lr - nb0)) * 32;
            float xv[32];
            #pragma unroll
            for (int j = 0; j < 32; j++) {
                float s = ar[j];
                #pragma unroll
                for (int i = 0; i < 31; i++)
                    if (i < j) s -= xv[i] * d[i][j];
                xv[j] = s * dinv[j];
                lrow[j] = xv[j];
            }
        }
    }
}

// ---------------- update: A22 -= L21 @ U12 (128x128 tiles, 2 CTA/SM) -----------
__global__ __launch_bounds__(256, 2) void update_kernel(int kb) {
    __shared__ float Bs[32][128];
    __shared__ float LsT[32][132];
    int m = blockIdx.z, tid = threadIdx.x;
    int col0 = kb * NB, nb0 = col0 + NB;
    int RC = N - nb0;
    const int* map = g_rowmap + m * N;
    float* A = g_lu + (size_t)m * NN;
    const float* U = g_u12 + (size_t)m * 32 * N;
    const float* L = g_l21 + (size_t)m * N * 32;
    int c0 = nb0 + blockIdx.x * 128;
    int r0p = blockIdx.y * 128;

    #pragma unroll
    for (int i = 0; i < 16; i++) {
        int l = tid + i * 256;
        int c = l & 127, kk = l >> 7;
        int cc = c0 + c;
        Bs[kk][c] = (cc < N) ? U[kk * N + cc] : 0.0f;
    }
    #pragma unroll
    for (int i = 0; i < 16; i++) {
        int l = tid + i * 256;
        int r = l >> 5, kk = l & 31;
        int p = r0p + r;
        LsT[kk][r] = (p < RC) ? L[(size_t)p * 32 + kk] : 0.0f;
    }
    __syncthreads();

    int tx = tid & 15, ty = tid >> 4;
    float acc[8][8] = {};
    #pragma unroll
    for (int kk = 0; kk < 32; kk++) {
        float a[8], b[8];
        *(float4*)&a[0] = *(const float4*)&LsT[kk][ty * 8];
        *(float4*)&a[4] = *(const float4*)&LsT[kk][ty * 8 + 4];
        *(float4*)&b[0] = *(const float4*)&Bs[kk][tx * 8];
        *(float4*)&b[4] = *(const float4*)&Bs[kk][tx * 8 + 4];
        #pragma unroll
        for (int i = 0; i < 8; i++)
            #pragma unroll
            for (int j = 0; j < 8; j++)
                acc[i][j] = fmaf(a[i], b[j], acc[i][j]);
    }
    int gc0 = c0 + tx * 8;
    if (gc0 < N) {
        #pragma unroll
        for (int i = 0; i < 8; i++) {
            int p = r0p + ty * 8 + i;
            if (p < RC) {
                float4* pp = (float4*)&A[(size_t)map[nb0 + p] * N + gc0];
                float4 v0 = pp[0], v1 = pp[1];
                v0.x -= acc[i][0]; v0.y -= acc[i][1]; v0.z -= acc[i][2]; v0.w -= acc[i][3];
                v1.x -= acc[i][4]; v1.y -= acc[i][5]; v1.z -= acc[i][6]; v1.w -= acc[i][7];
                pp[0] = v0; pp[1] = v1;
            }
        }
    }
}

// ---------------- top-8 + effective-weight collapse ----------------------------
__global__ void topk_kernel(const int* __restrict__ flags_i32,
                            const float* __restrict__ W1, const float* __restrict__ b1,
                            const float* __restrict__ W2, const float* __restrict__ b2) {
    if (threadIdx.x != 0) return;
    const unsigned char* flags_u8 = (const unsigned char*)flags_i32;
    int w0 = flags_i32[0];
    bool as_bytes = (w0 > 1) || (w0 < 0);
    int f[16];
    for (int i = 0; i < 16; i++)
        f[i] = as_bytes ? (flags_u8[i] != 0) : (flags_i32[i] != 0);
    int s = 0;
    for (int i = 0; i < 16; i++) s += f[i];
    g_gate = (s >= 4) ? 1 : 0;
    const float NEG_INF = -__int_as_float(0x7f800000);
    float sc[16];
    for (int i = 0; i < 16; i++) sc[i] = f[i] ? g_scores[i] : NEG_INF;
    bool used[16] = {};
    for (int k = 0; k < 8; k++) {
        float best = NEG_INF;
        int bi = -1;
        for (int i = 0; i < 16; i++)
            if (!used[i] && (bi < 0 || sc[i] > best)) { best = sc[i]; bi = i; }
        used[bi] = true;
        g_top[k] = bi;
    }
    for (int c = 0; c < 10; c++) {
        float a = 0.0f;
        for (int h = 0; h < 16; h++) a += W2[h] * W1[h * 10 + c];
        g_weff[c] = a;
    }
    float be = b2[0];
    for (int h = 0; h < 16; h++) be += W2[h] * b1[h];
    g_weff[10] = be;
}

// ---------------- Y combos -----------------------------------------------------
__global__ void ycombo_kernel(const float* __restrict__ x) {
    const float* X1 = x + (size_t)g_top[1] * NN;
    const float* X2 = x + (size_t)g_top[2] * NN;
    const float* X3 = x + (size_t)g_top[3] * NN;
    float w0 = g_weff[0], w1 = g_weff[1], w2 = g_weff[2];
    float w3 = g_weff[3], w4 = g_weff[4], w5 = g_weff[5];
    for (int e = blockIdx.x * blockDim.x + threadIdx.x; e < NN;
         e += gridDim.x * blockDim.x) {
        float a = X1[e], b = X2[e], c = X3[e];
        g_y[e]          = w0 * a + w1 * b + w2 * c;
        g_y[NN + e]     = w3 * b + w4 * c;
        g_y[2 * NN + e] = w5 * c;
    }
}

// ---------------- pair GEMM: X (1024x3072) @ Y (3072x1024), split-K=4 ----------
__global__ __launch_bounds__(256) void pair_gemm(const float* __restrict__ x) {
    __shared__ float As[16][132];
    __shared__ float Bs[16][128];
    int z = blockIdx.z;
    int row0 = blockIdx.y * 128, c0 = blockIdx.x * 128;
    const float* A0 = x + (size_t)g_top[0] * NN;
    const float* A1 = x + (size_t)g_top[1] * NN;
    const float* A2 = x + (size_t)g_top[2] * NN;
    int tid = threadIdx.x;
    float acc[8][8] = {};
    int k0 = z * 768;
    for (int kt = 0; kt < 48; kt++) {
        int kg = k0 + kt * 16;
        const float* Ap = (kg < 1024) ? A0 : ((kg < 2048) ? A1 : A2);
        int kl = kg & 1023;
        #pragma unroll
        for (int i = 0; i < 8; i++) {
            int l = tid + i * 256;
            int kk = l & 15, mm = l >> 4;
            As[kk][mm] = Ap[(size_t)(row0 + mm) * N + kl + kk];
        }
        #pragma unroll
        for (int i = 0; i < 8; i++) {
            int l = tid + i * 256;
            int nn = l & 127, kk = l >> 7;
            Bs[kk][nn] = g_y[(size_t)(kg + kk) * N + c0 + nn];
        }
        __syncthreads();
        int mm0 = (tid >> 4) * 8, nn0 = (tid & 15) * 8;
        #pragma unroll
        for (int kk = 0; kk < 16; kk++) {
            float a[8], b[8];
            *(float4*)&a[0] = *(const float4*)&As[kk][mm0];
            *(float4*)&a[4] = *(const float4*)&As[kk][mm0 + 4];
            *(float4*)&b[0] = *(const float4*)&Bs[kk][nn0];
            *(float4*)&b[4] = *(const float4*)&Bs[kk][nn0 + 4];
            #pragma unroll
            for (int i = 0; i < 8; i++)
                #pragma unroll
                for (int j = 0; j < 8; j++)
                    acc[i][j] = fmaf(a[i], b[j], acc[i][j]);
        }
        __syncthreads();
    }
    float* P = g_part + (size_t)z * NN;
    int mm0 = (tid >> 4) * 8, nn0 = (tid & 15) * 8;
    #pragma unroll
    for (int i = 0; i < 8; i++) {
        float4 v0 = {acc[i][0], acc[i][1], acc[i][2], acc[i][3]};
        float4 v1 = {acc[i][4], acc[i][5], acc[i][6], acc[i][7]};
        size_t off = (size_t)(row0 + mm0 + i) * N + c0 + nn0;
        *(float4*)&P[off] = v0;
        *(float4*)&P[off + 4] = v1;
    }
}

// ---------------- epilogue -----------------------------------------------------
__global__ void final_kernel(const float* __restrict__ x, float* __restrict__ out,
                             int out_size) {
    int gate = g_gate;
    const float* P4 = x + (size_t)g_top[4] * NN;
    const float* P5 = x + (size_t)g_top[5] * NN;
    const float* P6 = x + (size_t)g_top[6] * NN;
    const float* P7 = x + (size_t)g_top[7] * NN;
    float w6 = g_weff[6], w7 = g_weff[7], w8 = g_weff[8], w9 = g_weff[9];
    float be = g_weff[10];
    for (int i = blockIdx.x * blockDim.x + threadIdx.x; i < out_size;
         i += gridDim.x * blockDim.x) {
        if (i < NN) {
            float s = g_part[i] + g_part[NN + i] + g_part[2 * NN + i] + g_part[3 * NN + i]
                    + w6 * P4[i] + w7 * P5[i] + w8 * P6[i] + w9 * P7[i] + be;
            out[i] = gate ? (s / (1.0f + expf(-s))) : 0.0f;
        } else {
            out[i] = gate ? 1.0f : 0.0f;
        }
    }
}

// ---------------- host driver --------------------------------------------------
extern "C" void kernel_launch(void* const* d_in, const int* in_sizes, int n_in,
                              void* d_out, int out_size) {
    const float* x = (const float*)d_in[0];
    const int* flags = (const int*)d_in[1];
    const float* W1 = (const float*)d_in[2];
    const float* b1 = (const float*)d_in[3];
    const float* W2 = (const float*)d_in[4];
    const float* b2 = (const float*)d_in[5];
    float* out = (float*)d_out;

    init_kernel<<<2048, 256>>>((const float4*)x);

    for (int kb = 0; kb < 32; kb++) {
        panel_kernel<<<16, 256>>>(kb);
        int CC = N - NB * (kb + 1);
        if (CC > 0) {
            int Ru = N - NB * kb;
            int ct = (CC + 127) / 128;
            int rtB = (Ru > 128) ? (Ru - 128 + 127) / 128 : 0;
            lstage_kernel<<<dim3(ct + rtB, 16), 128>>>(kb, ct);
            update_kernel<<<dim3(ct, ct, 16), 256>>>(kb);
        }
    }

    topk_kernel<<<1, 32>>>(flags, W1, b1, W2, b2);
    ycombo_kernel<<<1024, 256>>>(x);
    pair_gemm<<<dim3(8, 8, 4), 256>>>(x);
    final_kernel<<<1024, 256>>>(x, out, out_size);
}